// round 11
// baseline (speedup 1.0000x reference)
#include <cuda_runtime.h>
#include <cuda_fp16.h>
#include <cstdint>

#define MAXN 100000
#define MAXE 1600000
#define HD 128
#define SLOPE 0.2f
#define SCAN_B 1024

// ---------------- scratch (device globals) ----------------
__device__ __half g_xp1h[(size_t)MAXN * HD];   // layer1 x@W1 in fp16
__device__ float g_es[MAXN];
__device__ float g_ed[MAXN];
__device__ float g_xp2[MAXN];
__device__ int   g_cs[MAXE];
__device__ int   g_cd[MAXE];
__device__ int   g_csr[MAXE];
__device__ int   g_deg[MAXN];      // re-zeroed each run by k_scanC
__device__ int   g_cur[MAXN];
__device__ int   g_scan[MAXN];
__device__ int   g_rowptr[MAXN + 1];
__device__ int   g_bsum[128];
__device__ int   g_boff[128];
__device__ int   g_cnt;            // re-zeroed each run by k_node1
__device__ unsigned g_tick;        // reset by scanA's last block

// ---------------- helpers ----------------
__device__ __forceinline__ float lrelu(float x) { return x > 0.f ? x : SLOPE * x; }

__device__ __forceinline__ uint32_t f2h2(float a, float b) {
    __half2 h = __floats2half2_rn(a, b);
    return *(uint32_t*)&h;
}

__device__ __forceinline__ void mma_f16(float* c, const uint32_t* a, const uint32_t* b) {
    asm volatile("mma.sync.aligned.m16n8k16.row.col.f32.f16.f16.f32 "
                 "{%0,%1,%2,%3}, {%4,%5,%6,%7}, {%8,%9}, {%0,%1,%2,%3};"
                 : "+f"(c[0]), "+f"(c[1]), "+f"(c[2]), "+f"(c[3])
                 : "r"(a[0]), "r"(a[1]), "r"(a[2]), "r"(a[3]), "r"(b[0]), "r"(b[1]));
}

// fp16 row gather: 4 dims per lane as uint2 -> float4 (fp32 math)
__device__ __forceinline__ float4 gather_h4(int row, int lane) {
    uint2 u = __ldg((const uint2*)&g_xp1h[(size_t)row * HD] + lane);
    float2 lo = __half22float2(*(__half2*)&u.x);
    float2 hi = __half22float2(*(__half2*)&u.y);
    return make_float4(lo.x, lo.y, hi.x, hi.y);
}

// ---------------- compact + degree ----------------
__global__ void k_deg(const int* __restrict__ ei, const int* __restrict__ nt, int E) {
    int Er = (E + 31) & ~31;
    int lane = threadIdx.x & 31;
    int stride = gridDim.x * blockDim.x;
    for (int i = blockIdx.x * blockDim.x + threadIdx.x; i < Er; i += stride) {
        int s = 0, d = 0;
        bool act = false;
        if (i < E) {
            s = ei[i];
            d = ei[E + i];
            act = (__ldg(&nt[s]) == 0) && (__ldg(&nt[d]) == 0);
        }
        unsigned ball = __ballot_sync(0xffffffffu, act);
        if (ball) {
            int leader = __ffs(ball) - 1;
            int base = 0;
            if (lane == leader) base = atomicAdd(&g_cnt, __popc(ball));
            base = __shfl_sync(0xffffffffu, base, leader);
            if (act) {
                int off = __popc(ball & ((1u << lane) - 1u));
                g_cs[base + off] = s;
                g_cd[base + off] = d;
                atomicAdd(&g_deg[d], 1);
            }
        }
    }
}

// ---------------- scan (shuffle-based, fused block-sum scan via last block) ----------------
__global__ void __launch_bounds__(SCAN_B) k_scanA(int N) {
    __shared__ int wsum[32];
    __shared__ bool isLast;
    int tid = threadIdx.x;
    int lane = tid & 31;
    int wid = tid >> 5;
    int i = blockIdx.x * SCAN_B + tid;
    int v = (i < N) ? g_deg[i] : 0;

#pragma unroll
    for (int off = 1; off < 32; off <<= 1) {
        int t = __shfl_up_sync(0xffffffffu, v, off);
        if (lane >= off) v += t;
    }
    if (lane == 31) wsum[wid] = v;
    __syncthreads();
    if (wid == 0) {
        int w = wsum[lane];
#pragma unroll
        for (int off = 1; off < 32; off <<= 1) {
            int t = __shfl_up_sync(0xffffffffu, w, off);
            if (lane >= off) w += t;
        }
        wsum[lane] = w;
    }
    __syncthreads();
    if (wid) v += wsum[wid - 1];

    if (i < N) g_scan[i] = v;
    if (tid == SCAN_B - 1) g_bsum[blockIdx.x] = v;

    __threadfence();
    __syncthreads();
    if (tid == 0) {
        unsigned t = atomicAdd(&g_tick, 1u);
        isLast = (t == gridDim.x - 1);
    }
    __syncthreads();
    if (isLast && wid == 0) {
        int nb = gridDim.x;
        int total = 0;
        for (int c = 0; c * 32 < nb; c++) {
            int idx = c * 32 + lane;
            int x = (idx < nb) ? g_bsum[idx] : 0;
#pragma unroll
            for (int off = 1; off < 32; off <<= 1) {
                int t2 = __shfl_up_sync(0xffffffffu, x, off);
                if (lane >= off) x += t2;
            }
            if (idx < nb) g_boff[idx] = x + total;
            total += __shfl_sync(0xffffffffu, x, 31);
        }
        if (lane == 0) g_tick = 0;
        __threadfence();
    }
}

__global__ void k_scanC(int N) {
    int i = blockIdx.x * blockDim.x + threadIdx.x;
    if (i < N) {
        int b = i >> 10;
        int off = b ? g_boff[b - 1] : 0;
        int incl = off + g_scan[i];
        g_rowptr[i + 1] = incl;
        g_cur[i] = incl - g_deg[i];
        g_deg[i] = 0;
        if (i == 0) g_rowptr[0] = 0;
    }
}

__global__ void k_scatter() {
    int cnt = g_cnt;
    int st = gridDim.x * blockDim.x;
    for (int i = blockIdx.x * blockDim.x + threadIdx.x; i < cnt; i += st) {
        int s = g_cs[i], d = g_cd[i];
        int pos = atomicAdd(&g_cur[d], 1);
        g_csr[pos] = s;
    }
}

// =======================================================================
// GEMM1: xp1 = emb[h] @ W1 via mma.sync m16n8k16 fp16 (fp32 accum).
// Full-K staging: A rows and W^T as fp16 [row][k], 68-word rows.
// 8 k-steps, one mainloop sync. Fused e_src/e_dst epilogue; fp16 output.
// =======================================================================
static constexpr int HKW = 68;                      // words per fp16 row (64 + 4 pad)
static constexpr int OPAD = 132;
static constexpr int SM_TOT = 2 * 128 * HKW * 4;    // 69632 B

__global__ void __launch_bounds__(256, 2)
k_gemm1_tc(const int* __restrict__ hidx, const float* __restrict__ emb,
           const float* __restrict__ W,
           const float* __restrict__ as1, const float* __restrict__ ad1, int N)
{
    extern __shared__ char smem[];
    uint32_t* aw = (uint32_t*)smem;                  // A: [128][HKW] words
    uint32_t* bw = aw + 128 * HKW;                   // W^T: [128][HKW] words
    float*    os = (float*)smem;                     // epilogue reuse [32][OPAD]

    int tid  = threadIdx.x;
    int lane = tid & 31;
    int wid  = tid >> 5;
    int g    = lane >> 2;
    int tg   = lane & 3;
    int m_base = (wid & 3) * 32;
    int n_base = (wid >> 2) * 64;
    int blk0 = blockIdx.x * 128;

    float acc[2][8][4];
#pragma unroll
    for (int mf = 0; mf < 2; mf++)
#pragma unroll
        for (int nf = 0; nf < 8; nf++)
#pragma unroll
            for (int q = 0; q < 4; q++) acc[mf][nf][q] = 0.f;

    // ---- stage A: thread -> (row = tid/2, half = tid&1), 64 floats -> 32 words ----
    {
        int r = tid >> 1, hf = tid & 1;
        int grow = blk0 + r;
        int hrow = (grow < N) ? __ldg(&hidx[grow]) : 0;
        const float4* ap = (const float4*)&emb[(size_t)hrow * HD + hf * 64];
        uint32_t* dst = &aw[r * HKW + hf * 32];
#pragma unroll
        for (int q = 0; q < 8; q++) {
            float4 x0 = __ldg(&ap[q * 2]);
            float4 x1 = __ldg(&ap[q * 2 + 1]);
            uint4 u = make_uint4(f2h2(x0.x, x0.y), f2h2(x0.z, x0.w),
                                 f2h2(x1.x, x1.y), f2h2(x1.z, x1.w));
            *(uint4*)&dst[q * 4] = u;
        }
    }
    // ---- stage W^T as [n][k-pair]: float4 row-pair loads, 8 iters ----
#pragma unroll
    for (int t = 0; t < 8; t++) {
        int i = tid + t * 256;        // 0..2047
        int kp = i >> 5;              // k-pair 0..63
        int n4 = (i & 31) * 4;        // n group of 4
        float4 r0 = __ldg((const float4*)&W[(size_t)(2 * kp) * HD + n4]);
        float4 r1 = __ldg((const float4*)&W[(size_t)(2 * kp + 1) * HD + n4]);
        bw[(n4 + 0) * HKW + kp] = f2h2(r0.x, r1.x);
        bw[(n4 + 1) * HKW + kp] = f2h2(r0.y, r1.y);
        bw[(n4 + 2) * HKW + kp] = f2h2(r0.z, r1.z);
        bw[(n4 + 3) * HKW + kp] = f2h2(r0.w, r1.w);
    }
    __syncthreads();

    // ---- 8 k-steps of K=16 ----
#pragma unroll
    for (int ks = 0; ks < 8; ks++) {
        int k0 = ks * 8;  // word offset (16 fp16 = 8 words)
        uint32_t af[2][4], bf[8][2];
#pragma unroll
        for (int mf = 0; mf < 2; mf++) {
            int m0 = m_base + mf * 16;
            af[mf][0] = aw[(m0 + g) * HKW + k0 + tg];
            af[mf][1] = aw[(m0 + g + 8) * HKW + k0 + tg];
            af[mf][2] = aw[(m0 + g) * HKW + k0 + 4 + tg];
            af[mf][3] = aw[(m0 + g + 8) * HKW + k0 + 4 + tg];
        }
#pragma unroll
        for (int nf = 0; nf < 8; nf++) {
            int n0 = n_base + nf * 8;
            bf[nf][0] = bw[(n0 + g) * HKW + k0 + tg];
            bf[nf][1] = bw[(n0 + g) * HKW + k0 + 4 + tg];
        }
#pragma unroll
        for (int mf = 0; mf < 2; mf++)
#pragma unroll
            for (int nf = 0; nf < 8; nf++)
                mma_f16(acc[mf][nf], af[mf], bf[nf]);
    }
    __syncthreads();

    // ---- epilogue: 4 row-groups of 32 through smem; fused es/ed dots ----
    float4 av = __ldg((const float4*)&as1[lane * 4]);
    float4 dv = __ldg((const float4*)&ad1[lane * 4]);
#pragma unroll
    for (int rg = 0; rg < 4; rg++) {
        if ((wid & 3) == rg) {
#pragma unroll
            for (int mf = 0; mf < 2; mf++) {
                int r0 = mf * 16 + g;
#pragma unroll
                for (int nf = 0; nf < 8; nf++) {
                    int c0 = n_base + nf * 8 + tg * 2;
                    os[r0 * OPAD + c0]           = acc[mf][nf][0];
                    os[r0 * OPAD + c0 + 1]       = acc[mf][nf][1];
                    os[(r0 + 8) * OPAD + c0]     = acc[mf][nf][2];
                    os[(r0 + 8) * OPAD + c0 + 1] = acc[mf][nf][3];
                }
            }
        }
        __syncthreads();
#pragma unroll
        for (int rr = 0; rr < 4; rr++) {
            int rl = wid * 4 + rr;
            int row = blk0 + rg * 32 + rl;
            float4 v = *(const float4*)&os[rl * OPAD + lane * 4];
            float ps = v.x * av.x + v.y * av.y + v.z * av.z + v.w * av.w;
            float pd = v.x * dv.x + v.y * dv.y + v.z * dv.z + v.w * dv.w;
#pragma unroll
            for (int off = 16; off; off >>= 1) {
                ps += __shfl_xor_sync(0xffffffffu, ps, off);
                pd += __shfl_xor_sync(0xffffffffu, pd, off);
            }
            if (row < N) {
                uint2 hv = make_uint2(f2h2(v.x, v.y), f2h2(v.z, v.w));
                *(uint2*)&g_xp1h[(size_t)row * HD + lane * 4] = hv;
                if (lane == 0) {
                    g_es[row] = ps;
                    g_ed[row] = pd;
                }
            }
        }
        __syncthreads();
    }
}

// =======================================================================
// Layer-1 fused node kernel (warp per node), single pass, 4-way batched
// fp16 row gathers. Fused xp2 = relu(out1 + b1) . W2.
// =======================================================================
__global__ void __launch_bounds__(256) k_node1(
    const float* __restrict__ b1, const float* __restrict__ W2, int N)
{
    if (blockIdx.x == 0 && threadIdx.x == 0) g_cnt = 0;   // reset for next run
    int lane = threadIdx.x & 31;
    int node = blockIdx.x * 8 + (threadIdx.x >> 5);
    if (node >= N) return;

    int r0 = __ldg(&g_rowptr[node]);
    int r1 = __ldg(&g_rowptr[node + 1]);
    float edv = g_ed[node];
    float sw = __expf(lrelu(g_es[node] + edv));

    float4 sv = gather_h4(node, lane);

    float4 accv = make_float4(0.f, 0.f, 0.f, 0.f);
    float den_part = 0.f;
    for (int base = r0; base < r1; base += 32) {
        int e = base + lane;
        float wgt = 0.f; int src = 0;
        if (e < r1) {
            src = g_csr[e];
            wgt = __expf(lrelu(__ldg(&g_es[src]) + edv));
            den_part += wgt;
        }
        int cnt = min(32, r1 - base);
        int j = 0;
        for (; j + 4 <= cnt; j += 4) {
            float w0 = __shfl_sync(0xffffffffu, wgt, j);
            float w1 = __shfl_sync(0xffffffffu, wgt, j + 1);
            float w2 = __shfl_sync(0xffffffffu, wgt, j + 2);
            float w3 = __shfl_sync(0xffffffffu, wgt, j + 3);
            int s0 = __shfl_sync(0xffffffffu, src, j);
            int s1 = __shfl_sync(0xffffffffu, src, j + 1);
            int s2 = __shfl_sync(0xffffffffu, src, j + 2);
            int s3 = __shfl_sync(0xffffffffu, src, j + 3);
            float4 v0 = gather_h4(s0, lane);
            float4 v1 = gather_h4(s1, lane);
            float4 v2 = gather_h4(s2, lane);
            float4 v3 = gather_h4(s3, lane);
            accv.x += w0 * v0.x + w1 * v1.x + w2 * v2.x + w3 * v3.x;
            accv.y += w0 * v0.y + w1 * v1.y + w2 * v2.y + w3 * v3.y;
            accv.z += w0 * v0.z + w1 * v1.z + w2 * v2.z + w3 * v3.z;
            accv.w += w0 * v0.w + w1 * v1.w + w2 * v2.w + w3 * v3.w;
        }
        for (; j < cnt; j++) {
            float wj = __shfl_sync(0xffffffffu, wgt, j);
            int   sj = __shfl_sync(0xffffffffu, src, j);
            float4 v = gather_h4(sj, lane);
            accv.x += wj * v.x; accv.y += wj * v.y;
            accv.z += wj * v.z; accv.w += wj * v.w;
        }
    }
#pragma unroll
    for (int off = 16; off; off >>= 1)
        den_part += __shfl_xor_sync(0xffffffffu, den_part, off);
    float inv = __frcp_rn(den_part + sw);

    accv.x = (accv.x + sw * sv.x) * inv;
    accv.y = (accv.y + sw * sv.y) * inv;
    accv.z = (accv.z + sw * sv.z) * inv;
    accv.w = (accv.w + sw * sv.w) * inv;

    float4 bb = __ldg((const float4*)&b1[lane * 4]);
    float4 ww = __ldg((const float4*)&W2[lane * 4]);
    float s = fmaxf(accv.x + bb.x, 0.f) * ww.x + fmaxf(accv.y + bb.y, 0.f) * ww.y +
              fmaxf(accv.z + bb.z, 0.f) * ww.z + fmaxf(accv.w + bb.w, 0.f) * ww.w;
#pragma unroll
    for (int off = 16; off; off >>= 1) s += __shfl_xor_sync(0xffffffffu, s, off);
    if (lane == 0) g_xp2[node] = s;
}

// =======================================================================
// Layer-2 fused node kernel (thread per node, OUT=1), single pass.
// =======================================================================
__global__ void k_node2(const float* __restrict__ as2, const float* __restrict__ ad2,
                        const float* __restrict__ b2, float* __restrict__ out, int N)
{
    int i = blockIdx.x * blockDim.x + threadIdx.x;
    if (i >= N) return;
    float a = __ldg(&as2[0]), b = __ldg(&ad2[0]);
    float xi = g_xp2[i];
    int r0 = g_rowptr[i], r1 = g_rowptr[i + 1];
    float xib = xi * b;
    float sw = __expf(lrelu(xi * a + xib));
    float den = sw, num = sw * xi;
    for (int e = r0; e < r1; e++) {
        float xs = __ldg(&g_xp2[g_csr[e]]);
        float w = __expf(lrelu(xs * a + xib));
        den += w;
        num += w * xs;
    }
    out[i] = num / den + __ldg(&b2[0]);
}

// ---------------- launch ----------------
extern "C" void kernel_launch(void* const* d_in, const int* in_sizes, int n_in,
                              void* d_out, int out_size) {
    const int*   h    = (const int*)d_in[0];
    const int*   ei   = (const int*)d_in[1];
    const int*   nt   = (const int*)d_in[2];
    const float* emb  = (const float*)d_in[3];
    const float* W1   = (const float*)d_in[4];
    const float* as1  = (const float*)d_in[5];
    const float* ad1  = (const float*)d_in[6];
    const float* b1   = (const float*)d_in[7];
    const float* W2   = (const float*)d_in[8];
    const float* as2  = (const float*)d_in[9];
    const float* ad2  = (const float*)d_in[10];
    const float* b2   = (const float*)d_in[11];
    float* out = (float*)d_out;

    int N = in_sizes[0];
    int E = in_sizes[1] / 2;
    int nb = (N + 255) / 256;
    int nscan = (N + SCAN_B - 1) / SCAN_B;

    static cudaStream_t s2 = nullptr;
    static cudaEvent_t evFork = nullptr, evJoin = nullptr;
    if (!s2) {
        cudaFuncSetAttribute(k_gemm1_tc, cudaFuncAttributeMaxDynamicSharedMemorySize, SM_TOT);
        cudaStreamCreateWithFlags(&s2, cudaStreamNonBlocking);
        cudaEventCreateWithFlags(&evFork, cudaEventDisableTiming);
        cudaEventCreateWithFlags(&evJoin, cudaEventDisableTiming);
    }

    // fork: GEMM1 on s2 concurrent with CSR build
    cudaEventRecord(evFork, 0);
    cudaStreamWaitEvent(s2, evFork, 0);
    k_gemm1_tc<<<(N + 127) / 128, 256, SM_TOT, s2>>>(h, emb, W1, as1, ad1, N);
    cudaEventRecord(evJoin, s2);

    // CSR build (main stream)
    k_deg<<<1024, 256>>>(ei, nt, E);
    k_scanA<<<nscan, SCAN_B>>>(N);
    k_scanC<<<nb, 256>>>(N);
    k_scatter<<<1024, 256>>>();

    cudaStreamWaitEvent(0, evJoin, 0);

    k_node1<<<(N + 7) / 8, 256>>>(b1, W2, N);
    k_node2<<<nb, 256>>>(as2, ad2, b2, out, N);
}

// round 12
// speedup vs baseline: 1.0238x; 1.0238x over previous
#include <cuda_runtime.h>
#include <cuda_fp16.h>
#include <cstdint>

#define MAXN 100000
#define MAXE 1600000
#define HD 128
#define SLOPE 0.2f
#define SCAN_B 1024

// ---------------- scratch (device globals) ----------------
__device__ __half g_xp1h[(size_t)MAXN * HD];   // layer1 x@W1 in fp16
__device__ float g_es[MAXN];
__device__ float g_ed[MAXN];
__device__ float g_xp2[MAXN];
__device__ int   g_cs[MAXE];
__device__ int   g_cd[MAXE];
__device__ int   g_csr[MAXE];
__device__ int   g_deg[MAXN];      // re-zeroed each run by k_scanC
__device__ int   g_cur[MAXN];
__device__ int   g_scan[MAXN];
__device__ int   g_rowptr[MAXN + 1];
__device__ int   g_bsum[128];
__device__ int   g_boff[128];
__device__ int   g_cnt;            // re-zeroed each run by k_node1
__device__ unsigned g_tick;        // reset by scanA's last block

// ---------------- helpers ----------------
__device__ __forceinline__ float lrelu(float x) { return x > 0.f ? x : SLOPE * x; }

__device__ __forceinline__ uint32_t f2tf32(float f) {
    uint32_t r; asm("cvt.rna.tf32.f32 %0, %1;" : "=r"(r) : "f"(f)); return r;
}

__device__ __forceinline__ uint32_t f2h2(float a, float b) {
    __half2 h = __floats2half2_rn(a, b);
    return *(uint32_t*)&h;
}

__device__ __forceinline__ void mma_tf32(float* c, const uint32_t* a, const uint32_t* b) {
    asm volatile("mma.sync.aligned.m16n8k8.row.col.f32.tf32.tf32.f32 "
                 "{%0,%1,%2,%3}, {%4,%5,%6,%7}, {%8,%9}, {%0,%1,%2,%3};"
                 : "+f"(c[0]), "+f"(c[1]), "+f"(c[2]), "+f"(c[3])
                 : "r"(a[0]), "r"(a[1]), "r"(a[2]), "r"(a[3]), "r"(b[0]), "r"(b[1]));
}

// fp16 row gather: 4 dims per lane as uint2 -> float4 (fp32 math)
__device__ __forceinline__ float4 gather_h4(int row, int lane) {
    uint2 u = __ldg((const uint2*)&g_xp1h[(size_t)row * HD] + lane);
    float2 lo = __half22float2(*(__half2*)&u.x);
    float2 hi = __half22float2(*(__half2*)&u.y);
    return make_float4(lo.x, lo.y, hi.x, hi.y);
}

// ---------------- compact + degree ----------------
__global__ void k_deg(const int* __restrict__ ei, const int* __restrict__ nt, int E) {
    int Er = (E + 31) & ~31;
    int lane = threadIdx.x & 31;
    int stride = gridDim.x * blockDim.x;
    for (int i = blockIdx.x * blockDim.x + threadIdx.x; i < Er; i += stride) {
        int s = 0, d = 0;
        bool act = false;
        if (i < E) {
            s = ei[i];
            d = ei[E + i];
            act = (__ldg(&nt[s]) == 0) && (__ldg(&nt[d]) == 0);
        }
        unsigned ball = __ballot_sync(0xffffffffu, act);
        if (ball) {
            int leader = __ffs(ball) - 1;
            int base = 0;
            if (lane == leader) base = atomicAdd(&g_cnt, __popc(ball));
            base = __shfl_sync(0xffffffffu, base, leader);
            if (act) {
                int off = __popc(ball & ((1u << lane) - 1u));
                g_cs[base + off] = s;
                g_cd[base + off] = d;
                atomicAdd(&g_deg[d], 1);
            }
        }
    }
}

// ---------------- scan ----------------
__global__ void __launch_bounds__(SCAN_B) k_scanA(int N) {
    __shared__ int wsum[32];
    __shared__ bool isLast;
    int tid = threadIdx.x;
    int lane = tid & 31;
    int wid = tid >> 5;
    int i = blockIdx.x * SCAN_B + tid;
    int v = (i < N) ? g_deg[i] : 0;

#pragma unroll
    for (int off = 1; off < 32; off <<= 1) {
        int t = __shfl_up_sync(0xffffffffu, v, off);
        if (lane >= off) v += t;
    }
    if (lane == 31) wsum[wid] = v;
    __syncthreads();
    if (wid == 0) {
        int w = wsum[lane];
#pragma unroll
        for (int off = 1; off < 32; off <<= 1) {
            int t = __shfl_up_sync(0xffffffffu, w, off);
            if (lane >= off) w += t;
        }
        wsum[lane] = w;
    }
    __syncthreads();
    if (wid) v += wsum[wid - 1];

    if (i < N) g_scan[i] = v;
    if (tid == SCAN_B - 1) g_bsum[blockIdx.x] = v;

    __threadfence();
    __syncthreads();
    if (tid == 0) {
        unsigned t = atomicAdd(&g_tick, 1u);
        isLast = (t == gridDim.x - 1);
    }
    __syncthreads();
    if (isLast && wid == 0) {
        int nb = gridDim.x;
        int total = 0;
        for (int c = 0; c * 32 < nb; c++) {
            int idx = c * 32 + lane;
            int x = (idx < nb) ? g_bsum[idx] : 0;
#pragma unroll
            for (int off = 1; off < 32; off <<= 1) {
                int t2 = __shfl_up_sync(0xffffffffu, x, off);
                if (lane >= off) x += t2;
            }
            if (idx < nb) g_boff[idx] = x + total;
            total += __shfl_sync(0xffffffffu, x, 31);
        }
        if (lane == 0) g_tick = 0;
        __threadfence();
    }
}

__global__ void k_scanC(int N) {
    int i = blockIdx.x * blockDim.x + threadIdx.x;
    if (i < N) {
        int b = i >> 10;
        int off = b ? g_boff[b - 1] : 0;
        int incl = off + g_scan[i];
        g_rowptr[i + 1] = incl;
        g_cur[i] = incl - g_deg[i];
        g_deg[i] = 0;
        if (i == 0) g_rowptr[0] = 0;
    }
}

__global__ void k_scatter() {
    int cnt = g_cnt;
    int st = gridDim.x * blockDim.x;
    for (int i = blockIdx.x * blockDim.x + threadIdx.x; i < cnt; i += st) {
        int s = g_cs[i], d = g_cd[i];
        int pos = atomicAdd(&g_cur[d], 1);
        g_csr[pos] = s;
    }
}

// =======================================================================
// GEMM1-mma (rows [0, M1)): tf32 m16n8k8 (R10-proven), fp16 output.
// =======================================================================
static constexpr int KPAD = 136;
static constexpr int OPAD = 132;
static constexpr int SM_TOT = 2 * 32 * KPAD * 4;   // 34816 B

__global__ void __launch_bounds__(256, 2)
k_gemm1_tc(const int* __restrict__ hidx, const float* __restrict__ emb,
           const float* __restrict__ W,
           const float* __restrict__ as1, const float* __restrict__ ad1, int N)
{
    extern __shared__ char smem[];
    uint32_t* xs = (uint32_t*)smem;                      // [32][KPAD]
    uint32_t* ws = (uint32_t*)(smem + 32 * KPAD * 4);    // [32][KPAD]
    float*    os = (float*)smem;                         // [32][OPAD] epilogue reuse

    int tid  = threadIdx.x;
    int lane = tid & 31;
    int wid  = tid >> 5;
    int g    = lane >> 2;
    int tg   = lane & 3;
    int m_base = (wid & 3) * 32;
    int n_base = (wid >> 2) * 64;
    int blk0 = blockIdx.x * 128;

    float acc[2][8][4];
#pragma unroll
    for (int mf = 0; mf < 2; mf++)
#pragma unroll
        for (int nf = 0; nf < 8; nf++)
#pragma unroll
            for (int q = 0; q < 4; q++) acc[mf][nf][q] = 0.f;

    int arow = tid >> 1;
    int ahalf = tid & 1;
    int grow = blk0 + arow;
    int hrow = (grow < N) ? __ldg(&hidx[grow]) : 0;
    const float4* aptr = (const float4*)&emb[(size_t)hrow * HD];

    int bkk = tid >> 3;
    int bseg = tid & 7;

    for (int kc = 0; kc < 4; kc++) {
#pragma unroll
        for (int q = 0; q < 4; q++) {
            float4 v = __ldg(&aptr[kc * 8 + ahalf * 4 + q]);
            int k = ahalf * 16 + q * 4;
            xs[(k + 0) * KPAD + arow] = f2tf32(v.x);
            xs[(k + 1) * KPAD + arow] = f2tf32(v.y);
            xs[(k + 2) * KPAD + arow] = f2tf32(v.z);
            xs[(k + 3) * KPAD + arow] = f2tf32(v.w);
        }
        {
            const float4* bptr = (const float4*)&W[(size_t)(kc * 32 + bkk) * HD + bseg * 16];
#pragma unroll
            for (int q = 0; q < 4; q++) {
                float4 v = __ldg(&bptr[q]);
                uint4 u = make_uint4(f2tf32(v.x), f2tf32(v.y), f2tf32(v.z), f2tf32(v.w));
                *(uint4*)&ws[bkk * KPAD + bseg * 16 + q * 4] = u;
            }
        }
        __syncthreads();

#pragma unroll
        for (int ks = 0; ks < 4; ks++) {
            int k0 = ks * 8;
            uint32_t af[2][4], bf[8][2];
#pragma unroll
            for (int mf = 0; mf < 2; mf++) {
                int m0 = m_base + mf * 16;
                af[mf][0] = xs[(k0 + tg) * KPAD + m0 + g];
                af[mf][1] = xs[(k0 + tg) * KPAD + m0 + g + 8];
                af[mf][2] = xs[(k0 + tg + 4) * KPAD + m0 + g];
                af[mf][3] = xs[(k0 + tg + 4) * KPAD + m0 + g + 8];
            }
#pragma unroll
            for (int nf = 0; nf < 8; nf++) {
                int n0 = n_base + nf * 8;
                bf[nf][0] = ws[(k0 + tg) * KPAD + n0 + g];
                bf[nf][1] = ws[(k0 + tg + 4) * KPAD + n0 + g];
            }
#pragma unroll
            for (int mf = 0; mf < 2; mf++)
#pragma unroll
                for (int nf = 0; nf < 8; nf++)
                    mma_tf32(acc[mf][nf], af[mf], bf[nf]);
        }
        __syncthreads();
    }

    float4 av = __ldg((const float4*)&as1[lane * 4]);
    float4 dv = __ldg((const float4*)&ad1[lane * 4]);
#pragma unroll
    for (int rg = 0; rg < 4; rg++) {
        if ((wid & 3) == rg) {
#pragma unroll
            for (int mf = 0; mf < 2; mf++) {
                int r0 = mf * 16 + g;
#pragma unroll
                for (int nf = 0; nf < 8; nf++) {
                    int c0 = n_base + nf * 8 + tg * 2;
                    os[r0 * OPAD + c0]           = acc[mf][nf][0];
                    os[r0 * OPAD + c0 + 1]       = acc[mf][nf][1];
                    os[(r0 + 8) * OPAD + c0]     = acc[mf][nf][2];
                    os[(r0 + 8) * OPAD + c0 + 1] = acc[mf][nf][3];
                }
            }
        }
        __syncthreads();
#pragma unroll
        for (int rr = 0; rr < 4; rr++) {
            int rl = wid * 4 + rr;
            int row = blk0 + rg * 32 + rl;
            float4 v = *(const float4*)&os[rl * OPAD + lane * 4];
            float ps = v.x * av.x + v.y * av.y + v.z * av.z + v.w * av.w;
            float pd = v.x * dv.x + v.y * dv.y + v.z * dv.z + v.w * dv.w;
#pragma unroll
            for (int off = 16; off; off >>= 1) {
                ps += __shfl_xor_sync(0xffffffffu, ps, off);
                pd += __shfl_xor_sync(0xffffffffu, pd, off);
            }
            if (row < N) {
                uint2 hv = make_uint2(f2h2(v.x, v.y), f2h2(v.z, v.w));
                *(uint2*)&g_xp1h[(size_t)row * HD + lane * 4] = hv;
                if (lane == 0) {
                    g_es[row] = ps;
                    g_ed[row] = pd;
                }
            }
        }
        __syncthreads();
    }
}

// =======================================================================
// GEMM1-simt (rows [base, N)): R1-proven fp32 SIMT GEMM, fp16 output.
// 256 thr, 64x128 tile, runs on the FMA pipe concurrently with the mma
// kernel's tensor-pipe work on co-resident SMs.
// =======================================================================
__global__ void __launch_bounds__(256, 2)
k_gemm1_simt(const int* __restrict__ hidx, const float* __restrict__ emb,
             const float* __restrict__ W,
             const float* __restrict__ as1, const float* __restrict__ ad1,
             int base, int N)
{
    __shared__ float xs[32][64];    // [k][m]
    __shared__ float ws[32][128];   // [k][n]

    int tid = threadIdx.x;
    int tx = tid & 31;
    int ty = tid >> 5;
    int c0 = tx * 4;
    int r0 = ty * 8;
    int m0 = base + blockIdx.x * 64;

    float acc[8][4];
#pragma unroll
    for (int r = 0; r < 8; r++)
#pragma unroll
        for (int c = 0; c < 4; c++) acc[r][c] = 0.f;

    int idx0 = tid * 2;
    int mA = idx0 >> 3;
    int rowA = m0 + mA;
    bool okA = rowA < N;
    int hA = okA ? __ldg(&hidx[rowA]) : 0;

    for (int kt = 0; kt < HD; kt += 32) {
#pragma unroll
        for (int j = 0; j < 2; j++) {
            int idx = idx0 + j;
            int kq = idx & 7;
            float4 v = make_float4(0.f, 0.f, 0.f, 0.f);
            if (okA) v = __ldg((const float4*)&emb[(size_t)hA * HD + kt + kq * 4]);
            xs[kq * 4 + 0][mA] = v.x;
            xs[kq * 4 + 1][mA] = v.y;
            xs[kq * 4 + 2][mA] = v.z;
            xs[kq * 4 + 3][mA] = v.w;
        }
#pragma unroll
        for (int t = 0; t < 4; t++) {
            int idx = tid + t * 256;
            int kk = idx >> 5, nq = idx & 31;
            *(float4*)&ws[kk][nq * 4] = __ldg((const float4*)&W[(size_t)(kt + kk) * HD + nq * 4]);
        }
        __syncthreads();

#pragma unroll 8
        for (int kk = 0; kk < 32; kk++) {
            float4 xa = *(float4*)&xs[kk][r0];
            float4 xb = *(float4*)&xs[kk][r0 + 4];
            float4 wq = *(float4*)&ws[kk][c0];
            float xv[8] = {xa.x, xa.y, xa.z, xa.w, xb.x, xb.y, xb.z, xb.w};
            float wv[4] = {wq.x, wq.y, wq.z, wq.w};
#pragma unroll
            for (int r = 0; r < 8; r++)
#pragma unroll
                for (int c = 0; c < 4; c++)
                    acc[r][c] += xv[r] * wv[c];
        }
        __syncthreads();
    }

    float4 av = __ldg((const float4*)&as1[c0]);
    float4 dv = __ldg((const float4*)&ad1[c0]);
#pragma unroll
    for (int r = 0; r < 8; r++) {
        int row = m0 + r0 + r;
        bool ok = row < N;
        if (ok) {
            uint2 hv = make_uint2(f2h2(acc[r][0], acc[r][1]), f2h2(acc[r][2], acc[r][3]));
            *(uint2*)&g_xp1h[(size_t)row * HD + c0] = hv;
        }
        float ps = acc[r][0] * av.x + acc[r][1] * av.y + acc[r][2] * av.z + acc[r][3] * av.w;
        float pd = acc[r][0] * dv.x + acc[r][1] * dv.y + acc[r][2] * dv.z + acc[r][3] * dv.w;
#pragma unroll
        for (int off = 16; off; off >>= 1) {
            ps += __shfl_xor_sync(0xffffffffu, ps, off);
            pd += __shfl_xor_sync(0xffffffffu, pd, off);
        }
        if (tx == 0 && ok) {
            g_es[row] = ps;
            g_ed[row] = pd;
        }
    }
}

// =======================================================================
// Layer-1 fused node kernel (warp per node), single pass, 4-way batched
// fp16 row gathers. Fused xp2 = relu(out1 + b1) . W2.
// =======================================================================
__global__ void __launch_bounds__(256) k_node1(
    const float* __restrict__ b1, const float* __restrict__ W2, int N)
{
    if (blockIdx.x == 0 && threadIdx.x == 0) g_cnt = 0;   // reset for next run
    int lane = threadIdx.x & 31;
    int node = blockIdx.x * 8 + (threadIdx.x >> 5);
    if (node >= N) return;

    int r0 = __ldg(&g_rowptr[node]);
    int r1 = __ldg(&g_rowptr[node + 1]);
    float edv = g_ed[node];
    float sw = __expf(lrelu(g_es[node] + edv));

    float4 sv = gather_h4(node, lane);

    float4 accv = make_float4(0.f, 0.f, 0.f, 0.f);
    float den_part = 0.f;
    for (int base = r0; base < r1; base += 32) {
        int e = base + lane;
        float wgt = 0.f; int src = 0;
        if (e < r1) {
            src = g_csr[e];
            wgt = __expf(lrelu(__ldg(&g_es[src]) + edv));
            den_part += wgt;
        }
        int cnt = min(32, r1 - base);
        int j = 0;
        for (; j + 4 <= cnt; j += 4) {
            float w0 = __shfl_sync(0xffffffffu, wgt, j);
            float w1 = __shfl_sync(0xffffffffu, wgt, j + 1);
            float w2 = __shfl_sync(0xffffffffu, wgt, j + 2);
            float w3 = __shfl_sync(0xffffffffu, wgt, j + 3);
            int s0 = __shfl_sync(0xffffffffu, src, j);
            int s1 = __shfl_sync(0xffffffffu, src, j + 1);
            int s2 = __shfl_sync(0xffffffffu, src, j + 2);
            int s3 = __shfl_sync(0xffffffffu, src, j + 3);
            float4 v0 = gather_h4(s0, lane);
            float4 v1 = gather_h4(s1, lane);
            float4 v2 = gather_h4(s2, lane);
            float4 v3 = gather_h4(s3, lane);
            accv.x += w0 * v0.x + w1 * v1.x + w2 * v2.x + w3 * v3.x;
            accv.y += w0 * v0.y + w1 * v1.y + w2 * v2.y + w3 * v3.y;
            accv.z += w0 * v0.z + w1 * v1.z + w2 * v2.z + w3 * v3.z;
            accv.w += w0 * v0.w + w1 * v1.w + w2 * v2.w + w3 * v3.w;
        }
        for (; j < cnt; j++) {
            float wj = __shfl_sync(0xffffffffu, wgt, j);
            int   sj = __shfl_sync(0xffffffffu, src, j);
            float4 v = gather_h4(sj, lane);
            accv.x += wj * v.x; accv.y += wj * v.y;
            accv.z += wj * v.z; accv.w += wj * v.w;
        }
    }
#pragma unroll
    for (int off = 16; off; off >>= 1)
        den_part += __shfl_xor_sync(0xffffffffu, den_part, off);
    float inv = __frcp_rn(den_part + sw);

    accv.x = (accv.x + sw * sv.x) * inv;
    accv.y = (accv.y + sw * sv.y) * inv;
    accv.z = (accv.z + sw * sv.z) * inv;
    accv.w = (accv.w + sw * sv.w) * inv;

    float4 bb = __ldg((const float4*)&b1[lane * 4]);
    float4 ww = __ldg((const float4*)&W2[lane * 4]);
    float s = fmaxf(accv.x + bb.x, 0.f) * ww.x + fmaxf(accv.y + bb.y, 0.f) * ww.y +
              fmaxf(accv.z + bb.z, 0.f) * ww.z + fmaxf(accv.w + bb.w, 0.f) * ww.w;
#pragma unroll
    for (int off = 16; off; off >>= 1) s += __shfl_xor_sync(0xffffffffu, s, off);
    if (lane == 0) g_xp2[node] = s;
}

// =======================================================================
// Layer-2 fused node kernel (thread per node, OUT=1), single pass.
// =======================================================================
__global__ void k_node2(const float* __restrict__ as2, const float* __restrict__ ad2,
                        const float* __restrict__ b2, float* __restrict__ out, int N)
{
    int i = blockIdx.x * blockDim.x + threadIdx.x;
    if (i >= N) return;
    float a = __ldg(&as2[0]), b = __ldg(&ad2[0]);
    float xi = g_xp2[i];
    int r0 = g_rowptr[i], r1 = g_rowptr[i + 1];
    float xib = xi * b;
    float sw = __expf(lrelu(xi * a + xib));
    float den = sw, num = sw * xi;
    for (int e = r0; e < r1; e++) {
        float xs = __ldg(&g_xp2[g_csr[e]]);
        float w = __expf(lrelu(xs * a + xib));
        den += w;
        num += w * xs;
    }
    out[i] = num / den + __ldg(&b2[0]);
}

// ---------------- launch ----------------
extern "C" void kernel_launch(void* const* d_in, const int* in_sizes, int n_in,
                              void* d_out, int out_size) {
    const int*   h    = (const int*)d_in[0];
    const int*   ei   = (const int*)d_in[1];
    const int*   nt   = (const int*)d_in[2];
    const float* emb  = (const float*)d_in[3];
    const float* W1   = (const float*)d_in[4];
    const float* as1  = (const float*)d_in[5];
    const float* ad1  = (const float*)d_in[6];
    const float* b1   = (const float*)d_in[7];
    const float* W2   = (const float*)d_in[8];
    const float* as2  = (const float*)d_in[9];
    const float* ad2  = (const float*)d_in[10];
    const float* b2   = (const float*)d_in[11];
    float* out = (float*)d_out;

    int N = in_sizes[0];
    int E = in_sizes[1] / 2;
    int nb = (N + 255) / 256;
    int nscan = (N + SCAN_B - 1) / SCAN_B;

    // M split: 55% to the tensor-pipe kernel, 45% to the FMA-pipe kernel
    int M1 = 55040;
    if (M1 > N) M1 = (N / 128) * 128;
    int simtRows = N - M1;

    static cudaStream_t s2 = nullptr, s3 = nullptr;
    static cudaEvent_t evFork = nullptr, evJoin2 = nullptr, evJoin3 = nullptr;
    if (!s2) {
        cudaFuncSetAttribute(k_gemm1_tc, cudaFuncAttributeMaxDynamicSharedMemorySize, SM_TOT);
        cudaStreamCreateWithFlags(&s2, cudaStreamNonBlocking);
        cudaStreamCreateWithFlags(&s3, cudaStreamNonBlocking);
        cudaEventCreateWithFlags(&evFork, cudaEventDisableTiming);
        cudaEventCreateWithFlags(&evJoin2, cudaEventDisableTiming);
        cudaEventCreateWithFlags(&evJoin3, cudaEventDisableTiming);
    }

    // fork: mma-GEMM on s2 (tensor pipe), SIMT-GEMM on s3 (FMA pipe),
    // CSR build on main — all concurrent
    cudaEventRecord(evFork, 0);
    cudaStreamWaitEvent(s2, evFork, 0);
    cudaStreamWaitEvent(s3, evFork, 0);
    k_gemm1_tc<<<(M1 + 127) / 128, 256, SM_TOT, s2>>>(h, emb, W1, as1, ad1, M1);
    cudaEventRecord(evJoin2, s2);
    if (simtRows > 0) {
        k_gemm1_simt<<<(simtRows + 63) / 64, 256, 0, s3>>>(h, emb, W1, as1, ad1, M1, N);
    }
    cudaEventRecord(evJoin3, s3);

    // CSR build (main stream)
    k_deg<<<1024, 256>>>(ei, nt, E);
    k_scanA<<<nscan, SCAN_B>>>(N);
    k_scanC<<<nb, 256>>>(N);
    k_scatter<<<1024, 256>>>();

    cudaStreamWaitEvent(0, evJoin2, 0);
    cudaStreamWaitEvent(0, evJoin3, 0);

    k_node1<<<(N + 7) / 8, 256>>>(b1, W2, N);
    k_node2<<<nb, 256>>>(as2, ad2, b2, out, N);
}

// round 13
// speedup vs baseline: 1.0487x; 1.0244x over previous
#include <cuda_runtime.h>
#include <cuda_fp16.h>
#include <cstdint>

#define MAXN 100000
#define MAXE 1600000
#define HD 128
#define SLOPE 0.2f
#define SCAN_B 1024

// ---------------- scratch (device globals) ----------------
__device__ __half g_xp1h[(size_t)MAXN * HD];   // layer1 x@W1 in fp16
__device__ float g_es[MAXN];
__device__ float g_ed[MAXN];
__device__ float g_xp2[MAXN];
__device__ int   g_cs[MAXE];
__device__ int   g_cd[MAXE];
__device__ int   g_csr[MAXE];
__device__ int   g_deg[MAXN];      // re-zeroed each run by k_scanC
__device__ int   g_cur[MAXN];
__device__ int   g_scan[MAXN];
__device__ int   g_rowptr[MAXN + 1];
__device__ int   g_bsum[128];
__device__ int   g_boff[128];
__device__ int   g_cnt;            // re-zeroed each run by k_node1
__device__ unsigned g_tick;        // reset by scanA's last block

// ---------------- helpers ----------------
__device__ __forceinline__ float lrelu(float x) { return x > 0.f ? x : SLOPE * x; }

__device__ __forceinline__ uint32_t f2tf32(float f) {
    uint32_t r; asm("cvt.rna.tf32.f32 %0, %1;" : "=r"(r) : "f"(f)); return r;
}

__device__ __forceinline__ uint32_t f2h2(float a, float b) {
    __half2 h = __floats2half2_rn(a, b);
    return *(uint32_t*)&h;
}

__device__ __forceinline__ void mma_tf32(float* c, const uint32_t* a, const uint32_t* b) {
    asm volatile("mma.sync.aligned.m16n8k8.row.col.f32.tf32.tf32.f32 "
                 "{%0,%1,%2,%3}, {%4,%5,%6,%7}, {%8,%9}, {%0,%1,%2,%3};"
                 : "+f"(c[0]), "+f"(c[1]), "+f"(c[2]), "+f"(c[3])
                 : "r"(a[0]), "r"(a[1]), "r"(a[2]), "r"(a[3]), "r"(b[0]), "r"(b[1]));
}

// fp16 row gather: 4 dims per lane as uint2 -> float4 (fp32 math)
__device__ __forceinline__ float4 gather_h4(int row, int lane) {
    uint2 u = __ldg((const uint2*)&g_xp1h[(size_t)row * HD] + lane);
    float2 lo = __half22float2(*(__half2*)&u.x);
    float2 hi = __half22float2(*(__half2*)&u.y);
    return make_float4(lo.x, lo.y, hi.x, hi.y);
}

// ---------------- compact + degree ----------------
__global__ void k_deg(const int* __restrict__ ei, const int* __restrict__ nt, int E) {
    int Er = (E + 31) & ~31;
    int lane = threadIdx.x & 31;
    int stride = gridDim.x * blockDim.x;
    for (int i = blockIdx.x * blockDim.x + threadIdx.x; i < Er; i += stride) {
        int s = 0, d = 0;
        bool act = false;
        if (i < E) {
            s = ei[i];
            d = ei[E + i];
            act = (__ldg(&nt[s]) == 0) && (__ldg(&nt[d]) == 0);
        }
        unsigned ball = __ballot_sync(0xffffffffu, act);
        if (ball) {
            int leader = __ffs(ball) - 1;
            int base = 0;
            if (lane == leader) base = atomicAdd(&g_cnt, __popc(ball));
            base = __shfl_sync(0xffffffffu, base, leader);
            if (act) {
                int off = __popc(ball & ((1u << lane) - 1u));
                g_cs[base + off] = s;
                g_cd[base + off] = d;
                atomicAdd(&g_deg[d], 1);
            }
        }
    }
}

// ---------------- scan ----------------
__global__ void __launch_bounds__(SCAN_B) k_scanA(int N) {
    __shared__ int wsum[32];
    __shared__ bool isLast;
    int tid = threadIdx.x;
    int lane = tid & 31;
    int wid = tid >> 5;
    int i = blockIdx.x * SCAN_B + tid;
    int v = (i < N) ? g_deg[i] : 0;

#pragma unroll
    for (int off = 1; off < 32; off <<= 1) {
        int t = __shfl_up_sync(0xffffffffu, v, off);
        if (lane >= off) v += t;
    }
    if (lane == 31) wsum[wid] = v;
    __syncthreads();
    if (wid == 0) {
        int w = wsum[lane];
#pragma unroll
        for (int off = 1; off < 32; off <<= 1) {
            int t = __shfl_up_sync(0xffffffffu, w, off);
            if (lane >= off) w += t;
        }
        wsum[lane] = w;
    }
    __syncthreads();
    if (wid) v += wsum[wid - 1];

    if (i < N) g_scan[i] = v;
    if (tid == SCAN_B - 1) g_bsum[blockIdx.x] = v;

    __threadfence();
    __syncthreads();
    if (tid == 0) {
        unsigned t = atomicAdd(&g_tick, 1u);
        isLast = (t == gridDim.x - 1);
    }
    __syncthreads();
    if (isLast && wid == 0) {
        int nb = gridDim.x;
        int total = 0;
        for (int c = 0; c * 32 < nb; c++) {
            int idx = c * 32 + lane;
            int x = (idx < nb) ? g_bsum[idx] : 0;
#pragma unroll
            for (int off = 1; off < 32; off <<= 1) {
                int t2 = __shfl_up_sync(0xffffffffu, x, off);
                if (lane >= off) x += t2;
            }
            if (idx < nb) g_boff[idx] = x + total;
            total += __shfl_sync(0xffffffffu, x, 31);
        }
        if (lane == 0) g_tick = 0;
        __threadfence();
    }
}

__global__ void k_scanC(int N) {
    int i = blockIdx.x * blockDim.x + threadIdx.x;
    if (i < N) {
        int b = i >> 10;
        int off = b ? g_boff[b - 1] : 0;
        int incl = off + g_scan[i];
        g_rowptr[i + 1] = incl;
        g_cur[i] = incl - g_deg[i];
        g_deg[i] = 0;
        if (i == 0) g_rowptr[0] = 0;
    }
}

__global__ void k_scatter() {
    int cnt = g_cnt;
    int st = gridDim.x * blockDim.x;
    for (int i = blockIdx.x * blockDim.x + threadIdx.x; i < cnt; i += st) {
        int s = g_cs[i], d = g_cd[i];
        int pos = atomicAdd(&g_cur[d], 1);
        g_csr[pos] = s;
    }
}

// =======================================================================
// GEMM1 (R10-proven): xp1 = emb[h] @ W1 via mma.sync tf32 (m16n8k8).
// 256 thr, 128x128 tile, K in 4 smem chunks of 32, 2 CTA/SM, fp16 output.
// =======================================================================
static constexpr int KPAD = 136;
static constexpr int OPAD = 132;
static constexpr int SM_TOT = 2 * 32 * KPAD * 4;   // 34816 B

__global__ void __launch_bounds__(256, 2)
k_gemm1_tc(const int* __restrict__ hidx, const float* __restrict__ emb,
           const float* __restrict__ W,
           const float* __restrict__ as1, const float* __restrict__ ad1, int N)
{
    extern __shared__ char smem[];
    uint32_t* xs = (uint32_t*)smem;                      // [32][KPAD]
    uint32_t* ws = (uint32_t*)(smem + 32 * KPAD * 4);    // [32][KPAD]
    float*    os = (float*)smem;                         // [32][OPAD] epilogue reuse

    int tid  = threadIdx.x;
    int lane = tid & 31;
    int wid  = tid >> 5;
    int g    = lane >> 2;
    int tg   = lane & 3;
    int m_base = (wid & 3) * 32;
    int n_base = (wid >> 2) * 64;
    int blk0 = blockIdx.x * 128;

    float acc[2][8][4];
#pragma unroll
    for (int mf = 0; mf < 2; mf++)
#pragma unroll
        for (int nf = 0; nf < 8; nf++)
#pragma unroll
            for (int q = 0; q < 4; q++) acc[mf][nf][q] = 0.f;

    int arow = tid >> 1;
    int ahalf = tid & 1;
    int grow = blk0 + arow;
    int hrow = (grow < N) ? __ldg(&hidx[grow]) : 0;
    const float4* aptr = (const float4*)&emb[(size_t)hrow * HD];

    int bkk = tid >> 3;
    int bseg = tid & 7;

    for (int kc = 0; kc < 4; kc++) {
#pragma unroll
        for (int q = 0; q < 4; q++) {
            float4 v = __ldg(&aptr[kc * 8 + ahalf * 4 + q]);
            int k = ahalf * 16 + q * 4;
            xs[(k + 0) * KPAD + arow] = f2tf32(v.x);
            xs[(k + 1) * KPAD + arow] = f2tf32(v.y);
            xs[(k + 2) * KPAD + arow] = f2tf32(v.z);
            xs[(k + 3) * KPAD + arow] = f2tf32(v.w);
        }
        {
            const float4* bptr = (const float4*)&W[(size_t)(kc * 32 + bkk) * HD + bseg * 16];
#pragma unroll
            for (int q = 0; q < 4; q++) {
                float4 v = __ldg(&bptr[q]);
                uint4 u = make_uint4(f2tf32(v.x), f2tf32(v.y), f2tf32(v.z), f2tf32(v.w));
                *(uint4*)&ws[bkk * KPAD + bseg * 16 + q * 4] = u;
            }
        }
        __syncthreads();

#pragma unroll
        for (int ks = 0; ks < 4; ks++) {
            int k0 = ks * 8;
            uint32_t af[2][4], bf[8][2];
#pragma unroll
            for (int mf = 0; mf < 2; mf++) {
                int m0 = m_base + mf * 16;
                af[mf][0] = xs[(k0 + tg) * KPAD + m0 + g];
                af[mf][1] = xs[(k0 + tg) * KPAD + m0 + g + 8];
                af[mf][2] = xs[(k0 + tg + 4) * KPAD + m0 + g];
                af[mf][3] = xs[(k0 + tg + 4) * KPAD + m0 + g + 8];
            }
#pragma unroll
            for (int nf = 0; nf < 8; nf++) {
                int n0 = n_base + nf * 8;
                bf[nf][0] = ws[(k0 + tg) * KPAD + n0 + g];
                bf[nf][1] = ws[(k0 + tg + 4) * KPAD + n0 + g];
            }
#pragma unroll
            for (int mf = 0; mf < 2; mf++)
#pragma unroll
                for (int nf = 0; nf < 8; nf++)
                    mma_tf32(acc[mf][nf], af[mf], bf[nf]);
        }
        __syncthreads();
    }

    float4 av = __ldg((const float4*)&as1[lane * 4]);
    float4 dv = __ldg((const float4*)&ad1[lane * 4]);
#pragma unroll
    for (int rg = 0; rg < 4; rg++) {
        if ((wid & 3) == rg) {
#pragma unroll
            for (int mf = 0; mf < 2; mf++) {
                int r0 = mf * 16 + g;
#pragma unroll
                for (int nf = 0; nf < 8; nf++) {
                    int c0 = n_base + nf * 8 + tg * 2;
                    os[r0 * OPAD + c0]           = acc[mf][nf][0];
                    os[r0 * OPAD + c0 + 1]       = acc[mf][nf][1];
                    os[(r0 + 8) * OPAD + c0]     = acc[mf][nf][2];
                    os[(r0 + 8) * OPAD + c0 + 1] = acc[mf][nf][3];
                }
            }
        }
        __syncthreads();
#pragma unroll
        for (int rr = 0; rr < 4; rr++) {
            int rl = wid * 4 + rr;
            int row = blk0 + rg * 32 + rl;
            float4 v = *(const float4*)&os[rl * OPAD + lane * 4];
            float ps = v.x * av.x + v.y * av.y + v.z * av.z + v.w * av.w;
            float pd = v.x * dv.x + v.y * dv.y + v.z * dv.z + v.w * dv.w;
#pragma unroll
            for (int off = 16; off; off >>= 1) {
                ps += __shfl_xor_sync(0xffffffffu, ps, off);
                pd += __shfl_xor_sync(0xffffffffu, pd, off);
            }
            if (row < N) {
                uint2 hv = make_uint2(f2h2(v.x, v.y), f2h2(v.z, v.w));
                *(uint2*)&g_xp1h[(size_t)row * HD + lane * 4] = hv;
                if (lane == 0) {
                    g_es[row] = ps;
                    g_ed[row] = pd;
                }
            }
        }
        __syncthreads();
    }
}

// =======================================================================
// Layer-1 fused node kernel (warp per node), single pass, 4-way batched
// fp16 row gathers. Fused xp2 = relu(out1 + b1) . W2.
// =======================================================================
__global__ void __launch_bounds__(256) k_node1(
    const float* __restrict__ b1, const float* __restrict__ W2, int N)
{
    if (blockIdx.x == 0 && threadIdx.x == 0) g_cnt = 0;   // reset for next run
    int lane = threadIdx.x & 31;
    int node = blockIdx.x * 8 + (threadIdx.x >> 5);
    if (node >= N) return;

    int r0 = __ldg(&g_rowptr[node]);
    int r1 = __ldg(&g_rowptr[node + 1]);
    float edv = g_ed[node];
    float sw = __expf(lrelu(g_es[node] + edv));

    float4 sv = gather_h4(node, lane);

    float4 accv = make_float4(0.f, 0.f, 0.f, 0.f);
    float den_part = 0.f;
    for (int base = r0; base < r1; base += 32) {
        int e = base + lane;
        float wgt = 0.f; int src = 0;
        if (e < r1) {
            src = g_csr[e];
            wgt = __expf(lrelu(__ldg(&g_es[src]) + edv));
            den_part += wgt;
        }
        int cnt = min(32, r1 - base);
        int j = 0;
        for (; j + 4 <= cnt; j += 4) {
            float w0 = __shfl_sync(0xffffffffu, wgt, j);
            float w1 = __shfl_sync(0xffffffffu, wgt, j + 1);
            float w2 = __shfl_sync(0xffffffffu, wgt, j + 2);
            float w3 = __shfl_sync(0xffffffffu, wgt, j + 3);
            int s0 = __shfl_sync(0xffffffffu, src, j);
            int s1 = __shfl_sync(0xffffffffu, src, j + 1);
            int s2 = __shfl_sync(0xffffffffu, src, j + 2);
            int s3 = __shfl_sync(0xffffffffu, src, j + 3);
            float4 v0 = gather_h4(s0, lane);
            float4 v1 = gather_h4(s1, lane);
            float4 v2 = gather_h4(s2, lane);
            float4 v3 = gather_h4(s3, lane);
            accv.x += w0 * v0.x + w1 * v1.x + w2 * v2.x + w3 * v3.x;
            accv.y += w0 * v0.y + w1 * v1.y + w2 * v2.y + w3 * v3.y;
            accv.z += w0 * v0.z + w1 * v1.z + w2 * v2.z + w3 * v3.z;
            accv.w += w0 * v0.w + w1 * v1.w + w2 * v2.w + w3 * v3.w;
        }
        for (; j < cnt; j++) {
            float wj = __shfl_sync(0xffffffffu, wgt, j);
            int   sj = __shfl_sync(0xffffffffu, src, j);
            float4 v = gather_h4(sj, lane);
            accv.x += wj * v.x; accv.y += wj * v.y;
            accv.z += wj * v.z; accv.w += wj * v.w;
        }
    }
#pragma unroll
    for (int off = 16; off; off >>= 1)
        den_part += __shfl_xor_sync(0xffffffffu, den_part, off);
    float inv = __frcp_rn(den_part + sw);

    accv.x = (accv.x + sw * sv.x) * inv;
    accv.y = (accv.y + sw * sv.y) * inv;
    accv.z = (accv.z + sw * sv.z) * inv;
    accv.w = (accv.w + sw * sv.w) * inv;

    float4 bb = __ldg((const float4*)&b1[lane * 4]);
    float4 ww = __ldg((const float4*)&W2[lane * 4]);
    float s = fmaxf(accv.x + bb.x, 0.f) * ww.x + fmaxf(accv.y + bb.y, 0.f) * ww.y +
              fmaxf(accv.z + bb.z, 0.f) * ww.z + fmaxf(accv.w + bb.w, 0.f) * ww.w;
#pragma unroll
    for (int off = 16; off; off >>= 1) s += __shfl_xor_sync(0xffffffffu, s, off);
    if (lane == 0) g_xp2[node] = s;
}

// =======================================================================
// Layer-2 fused node kernel (thread per node, OUT=1), single pass.
// =======================================================================
__global__ void k_node2(const float* __restrict__ as2, const float* __restrict__ ad2,
                        const float* __restrict__ b2, float* __restrict__ out, int N)
{
    int i = blockIdx.x * blockDim.x + threadIdx.x;
    if (i >= N) return;
    float a = __ldg(&as2[0]), b = __ldg(&ad2[0]);
    float xi = g_xp2[i];
    int r0 = g_rowptr[i], r1 = g_rowptr[i + 1];
    float xib = xi * b;
    float sw = __expf(lrelu(xi * a + xib));
    float den = sw, num = sw * xi;
    for (int e = r0; e < r1; e++) {
        float xs = __ldg(&g_xp2[g_csr[e]]);
        float w = __expf(lrelu(xs * a + xib));
        den += w;
        num += w * xs;
    }
    out[i] = num / den + __ldg(&b2[0]);
}

// ---------------- launch ----------------
extern "C" void kernel_launch(void* const* d_in, const int* in_sizes, int n_in,
                              void* d_out, int out_size) {
    const int*   h    = (const int*)d_in[0];
    const int*   ei   = (const int*)d_in[1];
    const int*   nt   = (const int*)d_in[2];
    const float* emb  = (const float*)d_in[3];
    const float* W1   = (const float*)d_in[4];
    const float* as1  = (const float*)d_in[5];
    const float* ad1  = (const float*)d_in[6];
    const float* b1   = (const float*)d_in[7];
    const float* W2   = (const float*)d_in[8];
    const float* as2  = (const float*)d_in[9];
    const float* ad2  = (const float*)d_in[10];
    const float* b2   = (const float*)d_in[11];
    float* out = (float*)d_out;

    int N = in_sizes[0];
    int E = in_sizes[1] / 2;
    int nb = (N + 255) / 256;
    int nscan = (N + SCAN_B - 1) / SCAN_B;

    static cudaStream_t s2 = nullptr;
    static cudaEvent_t evFork = nullptr, evJoin = nullptr;
    if (!s2) {
        cudaFuncSetAttribute(k_gemm1_tc, cudaFuncAttributeMaxDynamicSharedMemorySize, SM_TOT);
        cudaStreamCreateWithFlags(&s2, cudaStreamNonBlocking);
        cudaEventCreateWithFlags(&evFork, cudaEventDisableTiming);
        cudaEventCreateWithFlags(&evJoin, cudaEventDisableTiming);
    }

    // fork event first: GEMM (submitted 4th for ncu targeting) still runs
    // concurrently with the CSR chain in the captured graph.
    cudaEventRecord(evFork, 0);
    cudaStreamWaitEvent(s2, evFork, 0);

    // CSR build part 1 (main stream) — launches 1..3
    k_deg<<<1024, 256>>>(ei, nt, E);
    k_scanA<<<nscan, SCAN_B>>>(N);
    k_scanC<<<nb, 256>>>(N);

    // GEMM on s2 — launch 4 (lands in the ncu -s 5 -c 1 window)
    k_gemm1_tc<<<(N + 127) / 128, 256, SM_TOT, s2>>>(h, emb, W1, as1, ad1, N);
    cudaEventRecord(evJoin, s2);

    // CSR build part 2 — launch 5
    k_scatter<<<1024, 256>>>();

    cudaStreamWaitEvent(0, evJoin, 0);

    k_node1<<<(N + 7) / 8, 256>>>(b1, W2, N);
    k_node2<<<nb, 256>>>(as2, ad2, b2, out, N);
}